// round 9
// baseline (speedup 1.0000x reference)
#include <cuda_runtime.h>
#include <cuda_fp16.h>
#include <cstdint>
#include <cstddef>

// ============================================================================
// GraphKANLayer on GB300 — fp16 tensor path with FUSED fp32->fp16 A-conversion
// (baseline PTX ISA only; compute_103 target rejects tcgen05).
//
//   W2[o,f] = INV_SQRT2 * nl_w[f] * w_out[o,f]
//   c[o]    = b_out[o] + sum_f nl_b[f] * w_out[o,f]
//   Yt_h[b*64+o, j] = fp16(sum_f x[b,j,f]*W2[o,f])   (prep1, fp32 math)
//   out[b,m,o] = 2^-13 * (fp16(adj*2^13) @ Yt_h^T) + c[o]
//
// GEMM M=8192 N=256 K=8192, 128 CTAs (64m x 2n), tile 128x128, 8 warps of
// 64x32. A is read as fp32 directly from adj via LDG one chunk ahead,
// converted in registers (exact 2^13 scale, RN), and STS'd into the 6-stage
// fp16 ring; B arrives via cp.async. ONE __syncthreads per chunk: all stage
// writes (STS A, cp.async B for chunk i+5) are issued after the head barrier,
// which orders every warp's reads of the stage being overwritten.
// ============================================================================

#define FEAT 64
#define ODIM 64
#define NODES 8192
#define BATCH 4
#define NCOLS 256
#define INV_SQRT2F 0.70710678118654752440f
#define ADJ_SCALE 8192.0f
#define OUT_SCALE (1.0f / 8192.0f)

#define MT 128
#define NT 128
#define KCH 64                       // k per chunk: 64 halfs = 128B rows
#define STAGES 6
#define NCH (NODES / KCH)            // 128
#define A_BYTES (MT * KCH * 2)       // 16384
#define STAGE_BYTES (2 * A_BYTES)    // 32768
#define SMEM_DYN (STAGES * STAGE_BYTES)   // 192 KB

#define JT 16                        // prep1 j-tile

// ---- scratch (static device globals; cudaMalloc forbidden) ----
__device__ __align__(16) __half g_Yt_h[(size_t)NCOLS * NODES];    // 4 MB

// ---------------------------------------------------------------------------
// PTX helpers (baseline ISA)
// ---------------------------------------------------------------------------
static __device__ __forceinline__ uint32_t smem_u32(const void* p) {
    uint32_t a;
    asm("{ .reg .u64 t; cvta.to.shared.u64 t, %1; cvt.u32.u64 %0, t; }"
        : "=r"(a) : "l"(p));
    return a;
}

static __device__ __forceinline__ void cp_async16(uint32_t dst, const void* src) {
    asm volatile("cp.async.cg.shared.global [%0], [%1], 16;"
                 :: "r"(dst), "l"(src) : "memory");
}
static __device__ __forceinline__ void cp_commit() {
    asm volatile("cp.async.commit_group;" ::: "memory");
}
template <int N>
static __device__ __forceinline__ void cp_wait() {
    asm volatile("cp.async.wait_group %0;" :: "n"(N) : "memory");
}

static __device__ __forceinline__ void ldsm_x4(uint32_t& r0, uint32_t& r1,
                                               uint32_t& r2, uint32_t& r3,
                                               uint32_t addr) {
    asm volatile("ldmatrix.sync.aligned.m8n8.x4.shared.b16 {%0,%1,%2,%3}, [%4];"
                 : "=r"(r0), "=r"(r1), "=r"(r2), "=r"(r3) : "r"(addr));
}

static __device__ __forceinline__ void mma_f16(float* d, const uint32_t* a,
                                               const uint32_t* b) {
    asm volatile(
        "mma.sync.aligned.m16n8k16.row.col.f32.f16.f16.f32 "
        "{%0,%1,%2,%3}, {%4,%5,%6,%7}, {%8,%9}, {%0,%1,%2,%3};"
        : "+f"(d[0]), "+f"(d[1]), "+f"(d[2]), "+f"(d[3])
        : "r"(a[0]), "r"(a[1]), "r"(a[2]), "r"(a[3]), "r"(b[0]), "r"(b[1]));
}

static __device__ __forceinline__ void sts128(uint32_t addr, uint32_t x,
                                              uint32_t y, uint32_t z, uint32_t w) {
    asm volatile("st.shared.v4.b32 [%0], {%1,%2,%3,%4};"
                 :: "r"(addr), "r"(x), "r"(y), "r"(z), "r"(w) : "memory");
}

static __device__ __forceinline__ uint32_t swz(uint32_t off) {
    return off ^ ((off >> 3) & 0x70);
}

static __device__ __forceinline__ uint32_t h2_as_u32(__half2 h) {
    union { __half2 h2; uint32_t u; } c;
    c.h2 = h;
    return c.u;
}

// ---------------------------------------------------------------------------
// prep1: Yt_h[b*64+o][j] = fp16( sum_f x[b,j,f] * W2[o,f] )
// W2 computed in-block. block: 256 threads = (o=tid%64, b=tid/64), JT=16 j.
// ---------------------------------------------------------------------------
__global__ void __launch_bounds__(256) prep1_kernel(const float* __restrict__ x,
                                                    const float* __restrict__ nl_w,
                                                    const float* __restrict__ w_out) {
    __shared__ float xs[BATCH][JT][FEAT];
    __shared__ float w2s[ODIM * (FEAT + 1)];
    const int tid = threadIdx.x;
    const int j0 = blockIdx.x * JT;

    for (int i = tid; i < ODIM * FEAT; i += 256) {
        int o = i >> 6, f = i & 63;
        w2s[o * (FEAT + 1) + f] = INV_SQRT2F * nl_w[f] * w_out[i];
    }

    for (int i4 = tid; i4 < BATCH * JT * (FEAT / 4); i4 += 256) {
        int b = i4 >> 8;
        int r = i4 & 255;
        int j = r >> 4;
        int f4 = r & 15;
        ((float4*)&xs[b][j][0])[f4] =
            ((const float4*)(x + ((size_t)b * NODES + j0 + j) * FEAT))[f4];
    }
    __syncthreads();

    const int o = tid & 63;
    const int b = tid >> 6;

    float w2r[FEAT];
#pragma unroll
    for (int f = 0; f < FEAT; f++) w2r[f] = w2s[o * (FEAT + 1) + f];

    union { __half h[JT]; uint4 u[2]; } ov;
#pragma unroll
    for (int j = 0; j < JT; j++) {
        float acc = 0.f;
#pragma unroll
        for (int f4 = 0; f4 < FEAT / 4; f4++) {
            float4 xv = ((float4*)&xs[b][j][0])[f4];
            acc += xv.x * w2r[f4 * 4 + 0];
            acc += xv.y * w2r[f4 * 4 + 1];
            acc += xv.z * w2r[f4 * 4 + 2];
            acc += xv.w * w2r[f4 * 4 + 3];
        }
        ov.h[j] = __float2half_rn(acc);
    }

    __half* dst = g_Yt_h + (size_t)(b * ODIM + o) * NODES + j0;
    ((uint4*)dst)[0] = ov.u[0];
    ((uint4*)dst)[1] = ov.u[1];
}

// ---------------------------------------------------------------------------
// Fused GEMM: out = 2^-13 * (fp16(adj*2^13) @ Yt_h^T) + c
// grid 128 = 64 m-tiles x 2 n-tiles, block 256 (8 warps: 2m x 4n, 64x32 each)
// ---------------------------------------------------------------------------
__global__ void __launch_bounds__(256, 1)
gemm_kernel(const float* __restrict__ adj,
            const float* __restrict__ nl_b, const float* __restrict__ w_out,
            const float* __restrict__ b_out, float* __restrict__ out) {
    extern __shared__ char dynsmem[];
    __shared__ float sc[ODIM];

    const int tid = threadIdx.x;
    const int wid = tid >> 5;
    const int lane = tid & 31;
    const int m0 = (blockIdx.x >> 1) * MT;
    const int n0 = (blockIdx.x & 1) * NT;
    const int wm = wid >> 2;     // 0..1  (m band of 64)
    const int wn = wid & 3;      // 0..3  (n band of 32)

    const uint32_t smem0 = smem_u32(dynsmem);

    // ---- A producer mapping: thread t -> row r_a = t>>1, k-half h_a = t&1 ----
    const int r_a = tid >> 1;
    const int h_a = tid & 1;
    const float* aptr = adj + (size_t)(m0 + r_a) * NODES + h_a * 32;
    uint32_t sts_off[4];
#pragma unroll
    for (int s = 0; s < 4; s++)
        sts_off[s] = swz((uint32_t)(r_a * 128 + h_a * 64 + s * 16));

    // ---- B producer mapping: 4 x 16B cp.async per thread ----
    const int rb0 = tid >> 3;           // 0..31
    const int sg = tid & 7;             // 16B segment
    uint32_t bdst[4];
#pragma unroll
    for (int k = 0; k < 4; k++)
        bdst[k] = (uint32_t)A_BYTES + swz((uint32_t)((rb0 + 32 * k) * 128 + sg * 16));

    // ---- consumer fragment offsets (pre-swizzled) ----
    // A (m16k16 tile mi): x4 mats = r0-7 k0-7, r8-15 k0-7, r0-7 k8-15, r8-15 k8-15
    uint32_t pa[4];
    {
        int r15 = lane & 15;
        int h = lane >> 4;
#pragma unroll
        for (int mi = 0; mi < 4; mi++)
            pa[mi] = swz((uint32_t)((wm * 64 + mi * 16 + r15) * 128 + h * 16));
    }
    // B (two n8 tiles per x4): mats = even k0-7, even k8-15, odd k0-7, odd k8-15
    uint32_t pb[2];
    {
        int tile_sel = lane >> 4;
        int h = (lane >> 3) & 1;
        int rn = lane & 7;
#pragma unroll
        for (int nj = 0; nj < 2; nj++)
            pb[nj] = swz((uint32_t)((wn * 32 + (nj * 2 + tile_sel) * 8 + rn) * 128 + h * 16));
    }

    float acc[4][4][4];
#pragma unroll
    for (int mi = 0; mi < 4; mi++)
#pragma unroll
        for (int ni = 0; ni < 4; ni++)
#pragma unroll
            for (int q = 0; q < 4; q++) acc[mi][ni][q] = 0.f;

    float4 stg[8];      // A fp32 staging: one chunk (32 floats) in flight

    auto ldg_chunk = [&](int c) {
        const float4* p = (const float4*)(aptr + (size_t)c * KCH);
#pragma unroll
        for (int q = 0; q < 8; q++) stg[q] = p[q];
    };
    auto sts_chunk = [&](int c) {
        const uint32_t sa = smem0 + (uint32_t)(c % STAGES) * STAGE_BYTES;
#pragma unroll
        for (int s = 0; s < 4; s++) {
            float4 v0 = stg[2 * s + 0];
            float4 v1 = stg[2 * s + 1];
            sts128(sa + sts_off[s],
                   h2_as_u32(__floats2half2_rn(v0.x * ADJ_SCALE, v0.y * ADJ_SCALE)),
                   h2_as_u32(__floats2half2_rn(v0.z * ADJ_SCALE, v0.w * ADJ_SCALE)),
                   h2_as_u32(__floats2half2_rn(v1.x * ADJ_SCALE, v1.y * ADJ_SCALE)),
                   h2_as_u32(__floats2half2_rn(v1.z * ADJ_SCALE, v1.w * ADJ_SCALE)));
        }
    };
    auto load_B = [&](int c) {
        const uint32_t sbase = smem0 + (uint32_t)(c % STAGES) * STAGE_BYTES;
        const int kb = c * KCH;
#pragma unroll
        for (int k = 0; k < 4; k++)
            cp_async16(sbase + bdst[k],
                       g_Yt_h + (size_t)(n0 + rb0 + 32 * k) * NODES + kb + sg * 8);
    };

    // ---- prologue: chunks 0..4 (A: LDG->cvt->STS; B: cp.async) ----
#pragma unroll
    for (int c = 0; c < STAGES - 1; c++) {
        ldg_chunk(c);
        sts_chunk(c);
        load_B(c);
        cp_commit();
    }
    ldg_chunk(STAGES - 1);   // chunk 5 staged for iteration 0

    // bias vector (overlaps with in-flight loads)
    if (tid < ODIM) {
        float a = b_out[tid];
#pragma unroll 8
        for (int f = 0; f < FEAT; f++) a += nl_b[f] * w_out[tid * FEAT + f];
        sc[tid] = a;
    }

    uint32_t fa[2][4][4];
    uint32_t fb[2][4][2];

    for (int i = 0; i < NCH; i++) {
        cp_wait<4>();            // B chunk i resident (1 commit/iter, lookahead 5)
        __syncthreads();         // orders all warps' reads of stage (i-1)%6,
                                 // and makes chunk i's A-STS + B visible

        // ---- producer for chunk i+5 (writes stage (i-1)%6: safe post-sync) ----
        const int pc = i + STAGES - 1;
        if (pc < NCH) sts_chunk(pc);          // consumes stg (chunk pc)
        if (pc + 1 < NCH) ldg_chunk(pc + 1);  // refill stg for next iteration
        if (pc < NCH) load_B(pc);
        cp_commit();                          // empty group near tail: keeps count

        // ---- compute chunk i ----
        const uint32_t sbase = smem0 + (uint32_t)(i % STAGES) * STAGE_BYTES;

        auto fetch = [&](int s, int buf) {
            const uint32_t xo = (uint32_t)s << 5;   // k16 step: +32B, XOR-safe
#pragma unroll
            for (int mi = 0; mi < 4; mi++)
                ldsm_x4(fa[buf][mi][0], fa[buf][mi][1],
                        fa[buf][mi][2], fa[buf][mi][3],
                        sbase + (pa[mi] ^ xo));
#pragma unroll
            for (int nj = 0; nj < 2; nj++) {
                uint32_t r0, r1, r2, r3;
                ldsm_x4(r0, r1, r2, r3, sbase + A_BYTES + (pb[nj] ^ xo));
                fb[buf][nj * 2 + 0][0] = r0;
                fb[buf][nj * 2 + 0][1] = r1;
                fb[buf][nj * 2 + 1][0] = r2;
                fb[buf][nj * 2 + 1][1] = r3;
            }
        };

        fetch(0, 0);
#pragma unroll
        for (int s = 0; s < KCH / 16; s++) {        // 4 k16 steps
            if (s < KCH / 16 - 1) fetch(s + 1, (s + 1) & 1);
            const int bf = s & 1;
#pragma unroll
            for (int mi = 0; mi < 4; mi++)
#pragma unroll
                for (int ni = 0; ni < 4; ni++)
                    mma_f16(acc[mi][ni], fa[bf][mi], fb[bf][ni]);
        }
        // no tail barrier: next iteration's head sync orders stage reuse
    }

    // ---- epilogue: rescale + bias + scatter to (b, node, o) ----
    const int qr = lane >> 2;
    const int qc = lane & 3;
#pragma unroll
    for (int mi = 0; mi < 4; mi++) {
        const int row0 = m0 + wm * 64 + mi * 16 + qr;
#pragma unroll
        for (int ni = 0; ni < 4; ni++) {
            const int ng = n0 + wn * 32 + ni * 8 + qc * 2;
            const int b = ng >> 6;
            const int o = ng & 63;
            const float c0 = sc[o];
            const float c1 = sc[o + 1];
            float* d0 = out + ((size_t)b * NODES + row0) * ODIM + o;
            float2 v0 = make_float2(acc[mi][ni][0] * OUT_SCALE + c0,
                                    acc[mi][ni][1] * OUT_SCALE + c1);
            float2 v1 = make_float2(acc[mi][ni][2] * OUT_SCALE + c0,
                                    acc[mi][ni][3] * OUT_SCALE + c1);
            *(float2*)d0 = v0;
            *(float2*)(d0 + 8 * ODIM) = v1;   // row0 + 8
        }
    }
}

// ---------------------------------------------------------------------------
// launch
// ---------------------------------------------------------------------------
extern "C" void kernel_launch(void* const* d_in, const int* in_sizes, int n_in,
                              void* d_out, int out_size) {
    (void)in_sizes; (void)n_in; (void)out_size;
    const float* x     = (const float*)d_in[0];
    const float* adj   = (const float*)d_in[1];
    const float* nl_w  = (const float*)d_in[2];
    const float* nl_b  = (const float*)d_in[3];
    const float* w_out = (const float*)d_in[4];
    const float* b_out = (const float*)d_in[5];
    float* out = (float*)d_out;

    prep1_kernel<<<NODES / JT, 256>>>(x, nl_w, w_out);

    cudaFuncSetAttribute(gemm_kernel,
                         cudaFuncAttributeMaxDynamicSharedMemorySize, SMEM_DYN);
    gemm_kernel<<<128, 256, SMEM_DYN>>>(adj, nl_b, w_out, b_out, out);
}

// round 10
// speedup vs baseline: 1.2831x; 1.2831x over previous
#include <cuda_runtime.h>
#include <cuda_fp16.h>
#include <cstdint>
#include <cstddef>

// ============================================================================
// GraphKANLayer on GB300 — fp16 tensor-core path (baseline PTX ISA only;
// compute_103 target rejects tcgen05). Round-8 dataflow (separate conv,
// cp.async-only GEMM) + pair-chunk loop with ONE __syncthreads per 2 chunks.
//
//   W2[o,f] = INV_SQRT2 * nl_w[f] * w_out[o,f]
//   c[o]    = b_out[o] + sum_f nl_b[f] * w_out[o,f]
//   adj_h   = fp16(adj * 2^13)                      (conv, RN, exact scale)
//   Yt_h[b*64+o, j] = fp16(sum_f x[b,j,f]*W2[o,f])  (prep1, fp32 math)
//   out[b,m,o] = 2^-13 * (adj_h @ Yt_h^T) + c[o]    (m16n8k16 MMA, f32 acc)
//
// GEMM M=8192 N=256 K=8192. 128 CTAs (64m x 2n), tile 128x128, 8 warps of
// 64x32. K organized as 64 PAIRS of 64-wide chunks; 3 superstages x 64 KB.
// Per iteration: wait pair p -> sync -> cp.async pair p+2 -> 8 k16 MMA steps.
// ============================================================================

#define FEAT 64
#define ODIM 64
#define NODES 8192
#define BATCH 4
#define NCOLS 256
#define INV_SQRT2F 0.70710678118654752440f
#define ADJ_SCALE 8192.0f
#define OUT_SCALE (1.0f / 8192.0f)

#define MT 128
#define NT 128
#define KCH 64                        // halfs per chunk (128B rows)
#define NPAIR 64                      // 64 pairs of chunks = K 8192
#define A_BYTES (MT * KCH * 2)        // 16384 per chunk
#define CHUNK_BYTES (2 * A_BYTES)     // 32768 (A+B)
#define SUPER_BYTES (2 * CHUNK_BYTES) // 65536 (2 chunks)
#define NSUPER 3
#define SMEM_DYN (NSUPER * SUPER_BYTES)   // 192 KB

#define JT 16                         // prep1 j-tile

// ---- scratch (static device globals; cudaMalloc forbidden) ----
__device__ __align__(16) __half g_adj_h[(size_t)NODES * NODES];   // 128 MB
__device__ __align__(16) __half g_Yt_h[(size_t)NCOLS * NODES];    // 4 MB

// ---------------------------------------------------------------------------
// PTX helpers (baseline ISA)
// ---------------------------------------------------------------------------
static __device__ __forceinline__ uint32_t smem_u32(const void* p) {
    uint32_t a;
    asm("{ .reg .u64 t; cvta.to.shared.u64 t, %1; cvt.u32.u64 %0, t; }"
        : "=r"(a) : "l"(p));
    return a;
}

static __device__ __forceinline__ void cp_async16(uint32_t dst, const void* src) {
    asm volatile("cp.async.cg.shared.global [%0], [%1], 16;"
                 :: "r"(dst), "l"(src) : "memory");
}
static __device__ __forceinline__ void cp_commit() {
    asm volatile("cp.async.commit_group;" ::: "memory");
}
template <int N>
static __device__ __forceinline__ void cp_wait() {
    asm volatile("cp.async.wait_group %0;" :: "n"(N) : "memory");
}

static __device__ __forceinline__ void ldsm_x4(uint32_t& r0, uint32_t& r1,
                                               uint32_t& r2, uint32_t& r3,
                                               uint32_t addr) {
    asm volatile("ldmatrix.sync.aligned.m8n8.x4.shared.b16 {%0,%1,%2,%3}, [%4];"
                 : "=r"(r0), "=r"(r1), "=r"(r2), "=r"(r3) : "r"(addr));
}

static __device__ __forceinline__ void mma_f16(float* d, const uint32_t* a,
                                               const uint32_t* b) {
    asm volatile(
        "mma.sync.aligned.m16n8k16.row.col.f32.f16.f16.f32 "
        "{%0,%1,%2,%3}, {%4,%5,%6,%7}, {%8,%9}, {%0,%1,%2,%3};"
        : "+f"(d[0]), "+f"(d[1]), "+f"(d[2]), "+f"(d[3])
        : "r"(a[0]), "r"(a[1]), "r"(a[2]), "r"(a[3]), "r"(b[0]), "r"(b[1]));
}

static __device__ __forceinline__ uint32_t swz(uint32_t off) {
    return off ^ ((off >> 3) & 0x70);
}

static __device__ __forceinline__ uint32_t h2_as_u32(__half2 h) {
    union { __half2 h2; uint32_t u; } c;
    c.h2 = h;
    return c.u;
}

// ---------------------------------------------------------------------------
// conv: adj fp32 -> fp16 (scaled by 2^13, RN). Pure bandwidth (81% DRAM R8).
// ---------------------------------------------------------------------------
__global__ void __launch_bounds__(256) conv_kernel(const float* __restrict__ adj) {
    const size_t n8 = (size_t)NODES * NODES / 8;
    size_t idx = (size_t)blockIdx.x * 256 + threadIdx.x;
    const size_t stride = (size_t)gridDim.x * 256;
    for (size_t i = idx; i < n8; i += stride) {
        const float4* s = (const float4*)(adj + i * 8);
        float4 v0 = s[0];
        float4 v1 = s[1];
        uint4 o;
        o.x = h2_as_u32(__floats2half2_rn(v0.x * ADJ_SCALE, v0.y * ADJ_SCALE));
        o.y = h2_as_u32(__floats2half2_rn(v0.z * ADJ_SCALE, v0.w * ADJ_SCALE));
        o.z = h2_as_u32(__floats2half2_rn(v1.x * ADJ_SCALE, v1.y * ADJ_SCALE));
        o.w = h2_as_u32(__floats2half2_rn(v1.z * ADJ_SCALE, v1.w * ADJ_SCALE));
        *reinterpret_cast<uint4*>(&g_adj_h[i * 8]) = o;
    }
}

// ---------------------------------------------------------------------------
// prep1: Yt_h[b*64+o][j] = fp16( sum_f x[b,j,f] * W2[o,f] )
// ---------------------------------------------------------------------------
__global__ void __launch_bounds__(256) prep1_kernel(const float* __restrict__ x,
                                                    const float* __restrict__ nl_w,
                                                    const float* __restrict__ w_out) {
    __shared__ float xs[BATCH][JT][FEAT];
    __shared__ float w2s[ODIM * (FEAT + 1)];
    const int tid = threadIdx.x;
    const int j0 = blockIdx.x * JT;

    for (int i = tid; i < ODIM * FEAT; i += 256) {
        int o = i >> 6, f = i & 63;
        w2s[o * (FEAT + 1) + f] = INV_SQRT2F * nl_w[f] * w_out[i];
    }

    for (int i4 = tid; i4 < BATCH * JT * (FEAT / 4); i4 += 256) {
        int b = i4 >> 8;
        int r = i4 & 255;
        int j = r >> 4;
        int f4 = r & 15;
        ((float4*)&xs[b][j][0])[f4] =
            ((const float4*)(x + ((size_t)b * NODES + j0 + j) * FEAT))[f4];
    }
    __syncthreads();

    const int o = tid & 63;
    const int b = tid >> 6;

    float w2r[FEAT];
#pragma unroll
    for (int f = 0; f < FEAT; f++) w2r[f] = w2s[o * (FEAT + 1) + f];

    union { __half h[JT]; uint4 u[2]; } ov;
#pragma unroll
    for (int j = 0; j < JT; j++) {
        float acc = 0.f;
#pragma unroll
        for (int f4 = 0; f4 < FEAT / 4; f4++) {
            float4 xv = ((float4*)&xs[b][j][0])[f4];
            acc += xv.x * w2r[f4 * 4 + 0];
            acc += xv.y * w2r[f4 * 4 + 1];
            acc += xv.z * w2r[f4 * 4 + 2];
            acc += xv.w * w2r[f4 * 4 + 3];
        }
        ov.h[j] = __float2half_rn(acc);
    }

    __half* dst = g_Yt_h + (size_t)(b * ODIM + o) * NODES + j0;
    ((uint4*)dst)[0] = ov.u[0];
    ((uint4*)dst)[1] = ov.u[1];
}

// ---------------------------------------------------------------------------
// Main GEMM: out = 2^-13 * (adj_h @ Yt_h^T) + c
// grid 128 = 64 m-tiles x 2 n-tiles, block 256 (8 warps: 2m x 4n, 64x32 each)
// Pair loop: one wait + one sync per 2 chunks.
// ---------------------------------------------------------------------------
__global__ void __launch_bounds__(256, 1)
gemm_kernel(const float* __restrict__ nl_b, const float* __restrict__ w_out,
            const float* __restrict__ b_out, float* __restrict__ out) {
    extern __shared__ char dynsmem[];
    __shared__ float sc[ODIM];

    const int tid = threadIdx.x;
    const int wid = tid >> 5;
    const int lane = tid & 31;
    const int m0 = (blockIdx.x >> 1) * MT;
    const int n0 = (blockIdx.x & 1) * NT;
    const int wm = wid >> 2;     // 0..1  (m band of 64)
    const int wn = wid & 3;      // 0..3  (n band of 32)

    const uint32_t smem0 = smem_u32(dynsmem);

    // consumer fragment offsets (pre-swizzled), identical to round 8 (proven)
    uint32_t pa[4];
    {
        int r15 = lane & 15;
        int h = lane >> 4;
#pragma unroll
        for (int mi = 0; mi < 4; mi++)
            pa[mi] = swz((uint32_t)((wm * 64 + mi * 16 + r15) * 128 + h * 16));
    }
    uint32_t pb[2];
    {
        int tile_sel = lane >> 4;
        int h = (lane >> 3) & 1;
        int rn = lane & 7;
#pragma unroll
        for (int nj = 0; nj < 2; nj++)
            pb[nj] = swz((uint32_t)((wn * 32 + (nj * 2 + tile_sel) * 8 + rn) * 128 + h * 16));
    }

    float acc[4][4][4];
#pragma unroll
    for (int mi = 0; mi < 4; mi++)
#pragma unroll
        for (int ni = 0; ni < 4; ni++)
#pragma unroll
            for (int q = 0; q < 4; q++) acc[mi][ni][q] = 0.f;

    // per-thread cp.async mapping (one chunk): 8 x 16B; A rows then B rows
    const int mat = tid >> 7;            // warps 0-3: A, warps 4-7: B  (idx split)
    // Use same mapping as round 8: idx = tid + t*256 over 2048 segments.
    auto load_pair = [&](int p) {
        const uint32_t sbase = smem0 + (uint32_t)(p % NSUPER) * SUPER_BYTES;
#pragma unroll
        for (int half = 0; half < 2; half++) {     // two chunks of the pair
            const int kb = (2 * p + half) * KCH;
            const uint32_t cbase = sbase + (uint32_t)half * CHUNK_BYTES;
#pragma unroll
            for (int t = 0; t < 8; t++) {
                int idx = tid + t * 256;            // 0..2047
                int m_ = idx >> 10;                 // 0=A, 1=B
                int r = (idx >> 3) & 127;
                int seg = idx & 7;
                uint32_t dst = cbase + (uint32_t)m_ * A_BYTES +
                               swz((uint32_t)(r * 128 + seg * 16));
                const __half* src = m_
                    ? g_Yt_h + (size_t)(n0 + r) * NODES + kb + seg * 8
                    : g_adj_h + (size_t)(m0 + r) * NODES + kb + seg * 8;
                cp_async16(dst, src);
            }
        }
    };
    (void)mat;

    // prologue: pairs 0 and 1 in flight (one group each)
    load_pair(0); cp_commit();
    load_pair(1); cp_commit();

    // bias vector (overlaps with in-flight loads)
    if (tid < ODIM) {
        float a = b_out[tid];
#pragma unroll 8
        for (int f = 0; f < FEAT; f++) a += nl_b[f] * w_out[tid * FEAT + f];
        sc[tid] = a;
    }

    uint32_t fa[2][4][4];
    uint32_t fb[2][4][2];

    for (int p = 0; p < NPAIR; p++) {
        cp_wait<1>();            // pair p resident (1 group per pair, 2 in flight)
        __syncthreads();         // publish pair p; all readers of superstage
                                 // (p+2)%3 (consumed in iter p-1) have passed

        // producer: pair p+2 into superstage (p+2)%3  — safe post-sync
        if (p + 2 < NPAIR) load_pair(p + 2);
        cp_commit();             // unconditional: keeps group accounting fixed

        const uint32_t sbase = smem0 + (uint32_t)(p % NSUPER) * SUPER_BYTES;

        auto fetch = [&](int s, int buf) {        // s = 0..7 across the pair
            const uint32_t cb = sbase + (uint32_t)(s >> 2) * CHUNK_BYTES;
            const uint32_t xo = (uint32_t)(s & 3) << 5;   // k16 step, XOR-safe
#pragma unroll
            for (int mi = 0; mi < 4; mi++)
                ldsm_x4(fa[buf][mi][0], fa[buf][mi][1],
                        fa[buf][mi][2], fa[buf][mi][3],
                        cb + (pa[mi] ^ xo));
#pragma unroll
            for (int nj = 0; nj < 2; nj++) {
                uint32_t r0, r1, r2, r3;
                ldsm_x4(r0, r1, r2, r3, cb + A_BYTES + (pb[nj] ^ xo));
                fb[buf][nj * 2 + 0][0] = r0;
                fb[buf][nj * 2 + 0][1] = r1;
                fb[buf][nj * 2 + 1][0] = r2;
                fb[buf][nj * 2 + 1][1] = r3;
            }
        };

        fetch(0, 0);
#pragma unroll
        for (int s = 0; s < 8; s++) {             // 8 k16 steps (2 chunks)
            if (s < 7) fetch(s + 1, (s + 1) & 1);
            const int bf = s & 1;
#pragma unroll
            for (int mi = 0; mi < 4; mi++)
#pragma unroll
                for (int ni = 0; ni < 4; ni++)
                    mma_f16(acc[mi][ni], fa[bf][mi], fb[bf][ni]);
        }
        // no tail barrier: next head sync orders superstage reuse
    }

    // epilogue: rescale + bias + scatter to (b, node, o)
    const int qr = lane >> 2;
    const int qc = lane & 3;
#pragma unroll
    for (int mi = 0; mi < 4; mi++) {
        const int row0 = m0 + wm * 64 + mi * 16 + qr;
#pragma unroll
        for (int ni = 0; ni < 4; ni++) {
            const int ng = n0 + wn * 32 + ni * 8 + qc * 2;
            const int b = ng >> 6;
            const int o = ng & 63;
            const float c0 = sc[o];
            const float c1 = sc[o + 1];
            float* d0 = out + ((size_t)b * NODES + row0) * ODIM + o;
            float2 v0 = make_float2(acc[mi][ni][0] * OUT_SCALE + c0,
                                    acc[mi][ni][1] * OUT_SCALE + c1);
            float2 v1 = make_float2(acc[mi][ni][2] * OUT_SCALE + c0,
                                    acc[mi][ni][3] * OUT_SCALE + c1);
            *(float2*)d0 = v0;
            *(float2*)(d0 + 8 * ODIM) = v1;   // row0 + 8
        }
    }
}

// ---------------------------------------------------------------------------
// launch
// ---------------------------------------------------------------------------
extern "C" void kernel_launch(void* const* d_in, const int* in_sizes, int n_in,
                              void* d_out, int out_size) {
    (void)in_sizes; (void)n_in; (void)out_size;
    const float* x     = (const float*)d_in[0];
    const float* adj   = (const float*)d_in[1];
    const float* nl_w  = (const float*)d_in[2];
    const float* nl_b  = (const float*)d_in[3];
    const float* w_out = (const float*)d_in[4];
    const float* b_out = (const float*)d_in[5];
    float* out = (float*)d_out;

    conv_kernel<<<4096, 256>>>(adj);
    prep1_kernel<<<NODES / JT, 256>>>(x, nl_w, w_out);

    cudaFuncSetAttribute(gemm_kernel,
                         cudaFuncAttributeMaxDynamicSharedMemorySize, SMEM_DYN);
    gemm_kernel<<<128, 256, SMEM_DYN>>>(nl_b, w_out, b_out, out);
}

// round 11
// speedup vs baseline: 1.3064x; 1.0182x over previous
#include <cuda_runtime.h>
#include <cuda_fp16.h>
#include <cstdint>
#include <cstddef>

// ============================================================================
// GraphKANLayer on GB300 — fp16 tensor path, SPLIT-K x2 for 2-CTA/SM occupancy
// (baseline PTX ISA only; compute_103 target rejects tcgen05).
//
//   adj_h = fp16(adj * 2^13)                        (conv, RN, exact scale)
//   Yt_h[b*64+o, j] = fp16(sum_f x[b,j,f]*W2[o,f])  (prep1; also computes c[o])
//   part[ks] = adj_h[:, ksK:(ks+1)K] @ Yt_h[:, ksK:(ks+1)K]^T   (GEMM, f32 acc)
//   out = (part[0] + part[1]) * 2^-13 + c[o]        (reduce, fused bias)
//
// GEMM per CTA: M=128, N=128, K=4096. grid 256 = 64m x 2n x 2ks. 3-stage
// 32KB ring (96KB SMEM -> 2 CTAs/SM), __launch_bounds__(256,2) caps regs at
// 128 (single-buffered fragments). One sync per chunk; cross-CTA overlap
// hides barrier + fetch bubbles.
// ============================================================================

#define FEAT 64
#define ODIM 64
#define NODES 8192
#define BATCH 4
#define NCOLS 256
#define INV_SQRT2F 0.70710678118654752440f
#define ADJ_SCALE 8192.0f
#define OUT_SCALE (1.0f / 8192.0f)

#define MT 128
#define NT 128
#define KCH 64                        // halfs per chunk (128B rows)
#define KSPLIT 2
#define KPC 64                        // chunks per CTA (K=4096)
#define A_BYTES (MT * KCH * 2)        // 16384
#define STAGE_BYTES (2 * A_BYTES)     // 32768 (A+B)
#define NSTG 3
#define SMEM_DYN (NSTG * STAGE_BYTES) // 98304 -> 2 CTAs/SM

#define JT 16                         // prep1 j-tile

// ---- scratch (static device globals; cudaMalloc forbidden) ----
__device__ __align__(16) __half g_adj_h[(size_t)NODES * NODES];      // 128 MB
__device__ __align__(16) __half g_Yt_h[(size_t)NCOLS * NODES];       // 4 MB
__device__ __align__(16) float  g_part[KSPLIT][(size_t)NCOLS * NODES]; // 16 MB
__device__ float g_c[ODIM];

// ---------------------------------------------------------------------------
// PTX helpers (baseline ISA)
// ---------------------------------------------------------------------------
static __device__ __forceinline__ uint32_t smem_u32(const void* p) {
    uint32_t a;
    asm("{ .reg .u64 t; cvta.to.shared.u64 t, %1; cvt.u32.u64 %0, t; }"
        : "=r"(a) : "l"(p));
    return a;
}

static __device__ __forceinline__ void cp_async16(uint32_t dst, const void* src) {
    asm volatile("cp.async.cg.shared.global [%0], [%1], 16;"
                 :: "r"(dst), "l"(src) : "memory");
}
static __device__ __forceinline__ void cp_commit() {
    asm volatile("cp.async.commit_group;" ::: "memory");
}
template <int N>
static __device__ __forceinline__ void cp_wait() {
    asm volatile("cp.async.wait_group %0;" :: "n"(N) : "memory");
}

static __device__ __forceinline__ void ldsm_x4(uint32_t& r0, uint32_t& r1,
                                               uint32_t& r2, uint32_t& r3,
                                               uint32_t addr) {
    asm volatile("ldmatrix.sync.aligned.m8n8.x4.shared.b16 {%0,%1,%2,%3}, [%4];"
                 : "=r"(r0), "=r"(r1), "=r"(r2), "=r"(r3) : "r"(addr));
}

static __device__ __forceinline__ void mma_f16(float* d, const uint32_t* a,
                                               const uint32_t* b) {
    asm volatile(
        "mma.sync.aligned.m16n8k16.row.col.f32.f16.f16.f32 "
        "{%0,%1,%2,%3}, {%4,%5,%6,%7}, {%8,%9}, {%0,%1,%2,%3};"
        : "+f"(d[0]), "+f"(d[1]), "+f"(d[2]), "+f"(d[3])
        : "r"(a[0]), "r"(a[1]), "r"(a[2]), "r"(a[3]), "r"(b[0]), "r"(b[1]));
}

static __device__ __forceinline__ uint32_t swz(uint32_t off) {
    return off ^ ((off >> 3) & 0x70);
}

static __device__ __forceinline__ uint32_t h2_as_u32(__half2 h) {
    union { __half2 h2; uint32_t u; } c;
    c.h2 = h;
    return c.u;
}

// ---------------------------------------------------------------------------
// conv: adj fp32 -> fp16 (scaled by 2^13, RN). 82% DRAM in R10.
// ---------------------------------------------------------------------------
__global__ void __launch_bounds__(256) conv_kernel(const float* __restrict__ adj) {
    const size_t n8 = (size_t)NODES * NODES / 8;
    size_t idx = (size_t)blockIdx.x * 256 + threadIdx.x;
    const size_t stride = (size_t)gridDim.x * 256;
    for (size_t i = idx; i < n8; i += stride) {
        const float4* s = (const float4*)(adj + i * 8);
        float4 v0 = s[0];
        float4 v1 = s[1];
        uint4 o;
        o.x = h2_as_u32(__floats2half2_rn(v0.x * ADJ_SCALE, v0.y * ADJ_SCALE));
        o.y = h2_as_u32(__floats2half2_rn(v0.z * ADJ_SCALE, v0.w * ADJ_SCALE));
        o.z = h2_as_u32(__floats2half2_rn(v1.x * ADJ_SCALE, v1.y * ADJ_SCALE));
        o.w = h2_as_u32(__floats2half2_rn(v1.z * ADJ_SCALE, v1.w * ADJ_SCALE));
        *reinterpret_cast<uint4*>(&g_adj_h[i * 8]) = o;
    }
}

// ---------------------------------------------------------------------------
// prep1: Yt_h[b*64+o][j] = fp16( sum_f x[b,j,f] * W2[o,f] ); block 0 also
// computes the fused bias c[o] = b_out[o] + sum_f nl_b[f]*w_out[o,f].
// ---------------------------------------------------------------------------
__global__ void __launch_bounds__(256) prep1_kernel(const float* __restrict__ x,
                                                    const float* __restrict__ nl_w,
                                                    const float* __restrict__ nl_b,
                                                    const float* __restrict__ w_out,
                                                    const float* __restrict__ b_out) {
    __shared__ float xs[BATCH][JT][FEAT];
    __shared__ float w2s[ODIM * (FEAT + 1)];
    const int tid = threadIdx.x;
    const int j0 = blockIdx.x * JT;

    if (blockIdx.x == 0 && tid >= 64 && tid < 128) {
        int o = tid - 64;
        float a = b_out[o];
#pragma unroll 8
        for (int f = 0; f < FEAT; f++) a += nl_b[f] * w_out[o * FEAT + f];
        g_c[o] = a;
    }

    for (int i = tid; i < ODIM * FEAT; i += 256) {
        int o = i >> 6, f = i & 63;
        w2s[o * (FEAT + 1) + f] = INV_SQRT2F * nl_w[f] * w_out[i];
    }

    for (int i4 = tid; i4 < BATCH * JT * (FEAT / 4); i4 += 256) {
        int b = i4 >> 8;
        int r = i4 & 255;
        int j = r >> 4;
        int f4 = r & 15;
        ((float4*)&xs[b][j][0])[f4] =
            ((const float4*)(x + ((size_t)b * NODES + j0 + j) * FEAT))[f4];
    }
    __syncthreads();

    const int o = tid & 63;
    const int b = tid >> 6;

    float w2r[FEAT];
#pragma unroll
    for (int f = 0; f < FEAT; f++) w2r[f] = w2s[o * (FEAT + 1) + f];

    union { __half h[JT]; uint4 u[2]; } ov;
#pragma unroll
    for (int j = 0; j < JT; j++) {
        float acc = 0.f;
#pragma unroll
        for (int f4 = 0; f4 < FEAT / 4; f4++) {
            float4 xv = ((float4*)&xs[b][j][0])[f4];
            acc += xv.x * w2r[f4 * 4 + 0];
            acc += xv.y * w2r[f4 * 4 + 1];
            acc += xv.z * w2r[f4 * 4 + 2];
            acc += xv.w * w2r[f4 * 4 + 3];
        }
        ov.h[j] = __float2half_rn(acc);
    }

    __half* dst = g_Yt_h + (size_t)(b * ODIM + o) * NODES + j0;
    ((uint4*)dst)[0] = ov.u[0];
    ((uint4*)dst)[1] = ov.u[1];
}

// ---------------------------------------------------------------------------
// Split-K GEMM: part[ks] += adj_h[m-rows, Kslice] @ Yt_h[n-rows, Kslice]^T
// grid 256 = (m 64) x (n 2) x (ks 2); block 256 (8 warps: 2m x 4n, 64x32)
// ---------------------------------------------------------------------------
__global__ void __launch_bounds__(256, 2)
gemm_kernel() {
    extern __shared__ char dynsmem[];

    const int tid = threadIdx.x;
    const int wid = tid >> 5;
    const int lane = tid & 31;
    const int ks = blockIdx.x & 1;
    const int n0 = ((blockIdx.x >> 1) & 1) * NT;
    const int m0 = (blockIdx.x >> 2) * MT;
    const int k0 = ks * (NODES / KSPLIT);
    const int wm = wid >> 2;     // 0..1  (m band of 64)
    const int wn = wid & 3;      // 0..3  (n band of 32)

    const uint32_t smem0 = smem_u32(dynsmem);

    // consumer fragment offsets (pre-swizzled) — proven in R8/R10
    uint32_t pa[4];
    {
        int r15 = lane & 15;
        int h = lane >> 4;
#pragma unroll
        for (int mi = 0; mi < 4; mi++)
            pa[mi] = swz((uint32_t)((wm * 64 + mi * 16 + r15) * 128 + h * 16));
    }
    uint32_t pb[2];
    {
        int tile_sel = lane >> 4;
        int h = (lane >> 3) & 1;
        int rn = lane & 7;
#pragma unroll
        for (int nj = 0; nj < 2; nj++)
            pb[nj] = swz((uint32_t)((wn * 32 + (nj * 2 + tile_sel) * 8 + rn) * 128 + h * 16));
    }

    float acc[4][4][4];
#pragma unroll
    for (int mi = 0; mi < 4; mi++)
#pragma unroll
        for (int ni = 0; ni < 4; ni++)
#pragma unroll
            for (int q = 0; q < 4; q++) acc[mi][ni][q] = 0.f;

    // per-thread cp.async mapping: 8 x 16B (t=0..3 -> A, t=4..7 -> B)
    auto load_chunk = [&](int c) {
        const uint32_t sbase = smem0 + (uint32_t)(c % NSTG) * STAGE_BYTES;
        const int kb = k0 + c * KCH;
#pragma unroll
        for (int t = 0; t < 8; t++) {
            int idx = tid + t * 256;            // 0..2047
            int m_ = idx >> 10;                 // 0=A, 1=B
            int r = (idx >> 3) & 127;
            int seg = idx & 7;
            uint32_t dst = sbase + (uint32_t)m_ * A_BYTES +
                           swz((uint32_t)(r * 128 + seg * 16));
            const __half* src = m_
                ? g_Yt_h + (size_t)(n0 + r) * NODES + kb + seg * 8
                : g_adj_h + (size_t)(m0 + r) * NODES + kb + seg * 8;
            cp_async16(dst, src);
        }
    };

    // prologue: chunks 0,1 in flight (one group each)
    load_chunk(0); cp_commit();
    load_chunk(1); cp_commit();

    uint32_t fa[4][4];
    uint32_t fb[4][2];

    for (int i = 0; i < KPC; i++) {
        cp_wait<1>();            // chunk i resident (1 group/chunk, 2 in flight)
        __syncthreads();         // readers of stage (i+2)%3 (iter i-1) passed

        const uint32_t sbase = smem0 + (uint32_t)(i % NSTG) * STAGE_BYTES;

        auto fetch = [&](int s) {
            const uint32_t xo = (uint32_t)s << 5;   // k16 step, XOR-safe
#pragma unroll
            for (int mi = 0; mi < 4; mi++)
                ldsm_x4(fa[mi][0], fa[mi][1], fa[mi][2], fa[mi][3],
                        sbase + (pa[mi] ^ xo));
#pragma unroll
            for (int nj = 0; nj < 2; nj++) {
                uint32_t r0, r1, r2, r3;
                ldsm_x4(r0, r1, r2, r3, sbase + A_BYTES + (pb[nj] ^ xo));
                fb[nj * 2 + 0][0] = r0;
                fb[nj * 2 + 0][1] = r1;
                fb[nj * 2 + 1][0] = r2;
                fb[nj * 2 + 1][1] = r3;
            }
        };

        fetch(0);                         // LDSM ahead of producer LDGSTS burst
        if (i + 2 < KPC) load_chunk(i + 2);
        cp_commit();                      // unconditional: fixed group count

#pragma unroll
        for (int s = 0; s < 4; s++) {     // 4 k16 steps, single-buffered frags
            if (s > 0) fetch(s);
#pragma unroll
            for (int mi = 0; mi < 4; mi++)
#pragma unroll
                for (int ni = 0; ni < 4; ni++)
                    mma_f16(acc[mi][ni], fa[mi], fb[ni]);
        }
        // no tail barrier: next head sync orders stage reuse
    }

    // epilogue: raw partial sums to g_part[ks] (bias/rescale in reduce)
    const int qr = lane >> 2;
    const int qc = lane & 3;
    float* part = &g_part[ks][0];
#pragma unroll
    for (int mi = 0; mi < 4; mi++) {
        const int row0 = m0 + wm * 64 + mi * 16 + qr;
#pragma unroll
        for (int ni = 0; ni < 4; ni++) {
            const int ng = n0 + wn * 32 + ni * 8 + qc * 2;
            const int b = ng >> 6;
            const int o = ng & 63;
            float* d0 = part + ((size_t)b * NODES + row0) * ODIM + o;
            *(float2*)d0 = make_float2(acc[mi][ni][0], acc[mi][ni][1]);
            *(float2*)(d0 + 8 * ODIM) = make_float2(acc[mi][ni][2], acc[mi][ni][3]);
        }
    }
}

// ---------------------------------------------------------------------------
// reduce: out = (part0 + part1) * 2^-13 + c[o]
// ---------------------------------------------------------------------------
__global__ void __launch_bounds__(256) reduce_kernel(float* __restrict__ out) {
    const size_t i4 = (size_t)blockIdx.x * 256 + threadIdx.x;  // float4 index
    const size_t e = i4 * 4;                                   // 4-aligned
    float4 p0 = *(const float4*)&g_part[0][e];
    float4 p1 = *(const float4*)&g_part[1][e];
    float4 c = *(const float4*)(g_c + (int)(e & 63));
    float4 r;
    r.x = (p0.x + p1.x) * OUT_SCALE + c.x;
    r.y = (p0.y + p1.y) * OUT_SCALE + c.y;
    r.z = (p0.z + p1.z) * OUT_SCALE + c.z;
    r.w = (p0.w + p1.w) * OUT_SCALE + c.w;
    *(float4*)(out + e) = r;
}

// ---------------------------------------------------------------------------
// launch
// ---------------------------------------------------------------------------
extern "C" void kernel_launch(void* const* d_in, const int* in_sizes, int n_in,
                              void* d_out, int out_size) {
    (void)in_sizes; (void)n_in; (void)out_size;
    const float* x     = (const float*)d_in[0];
    const float* adj   = (const float*)d_in[1];
    const float* nl_w  = (const float*)d_in[2];
    const float* nl_b  = (const float*)d_in[3];
    const float* w_out = (const float*)d_in[4];
    const float* b_out = (const float*)d_in[5];
    float* out = (float*)d_out;

    conv_kernel<<<4096, 256>>>(adj);
    prep1_kernel<<<NODES / JT, 256>>>(x, nl_w, nl_b, w_out, b_out);

    cudaFuncSetAttribute(gemm_kernel,
                         cudaFuncAttributeMaxDynamicSharedMemorySize, SMEM_DYN);
    gemm_kernel<<<256, 256, SMEM_DYN>>>();

    reduce_kernel<<<(NCOLS * NODES) / (256 * 4), 256>>>(out);
}

// round 14
// speedup vs baseline: 1.5529x; 1.1887x over previous
#include <cuda_runtime.h>
#include <cuda_fp16.h>
#include <cstdint>
#include <cstddef>

// ============================================================================
// GraphKANLayer on GB300 — fp16 tensor path, split-K x2, FUSED fp32->fp16
// A-conversion with COALESCED LDG (fixes R9's 32-wavefront/instr mapping).
// Baseline PTX ISA only (compute_103 target rejects tcgen05).
//
//   Yt_h[b*64+o, j] = fp16(sum_f x[b,j,f]*W2[o,f])  (prep1; also computes c[o])
//   part[ks] = fp16(adj*2^13)[:,Kslice] @ Yt_h[:,Kslice]^T   (GEMM, f32 acc)
//   out = (part[0]+part[1]) * 2^-13 + c[o]          (reduce, fused bias)
//
// GEMM per CTA: M=128,N=128,K=4096. grid 256 = 64m x 2n x 2ks. 3-stage 32KB
// ring (96KB -> 2 CTAs/SM). A: LDG.128 fp32 (coalesced, chunk i+2 issued at
// head of iter i), cvt 2^13 RN mid-iteration, STS.64 into ring. B: cp.async.
// One __syncthreads per chunk; cross-CTA overlap hides bubbles.
// ============================================================================

#define FEAT 64
#define ODIM 64
#define NODES 8192
#define BATCH 4
#define NCOLS 256
#define INV_SQRT2F 0.70710678118654752440f
#define ADJ_SCALE 8192.0f
#define OUT_SCALE (1.0f / 8192.0f)

#define MT 128
#define NT 128
#define KCH 64                        // halfs per chunk (128B fp16 rows)
#define KSPLIT 2
#define KPC 64                        // chunks per CTA (K=4096)
#define A_BYTES (MT * KCH * 2)        // 16384 (fp16 A half of stage)
#define STAGE_BYTES (2 * A_BYTES)     // 32768 (A+B)
#define NSTG 3
#define SMEM_DYN (NSTG * STAGE_BYTES) // 98304 -> 2 CTAs/SM

#define JT 16                         // prep1 j-tile

// ---- scratch (static device globals; cudaMalloc forbidden) ----
__device__ __align__(16) __half g_Yt_h[(size_t)NCOLS * NODES];         // 4 MB
__device__ __align__(16) float  g_part[KSPLIT][(size_t)NCOLS * NODES]; // 16 MB
__device__ float g_c[ODIM];

// ---------------------------------------------------------------------------
// PTX helpers (baseline ISA)
// ---------------------------------------------------------------------------
static __device__ __forceinline__ uint32_t smem_u32(const void* p) {
    uint32_t a;
    asm("{ .reg .u64 t; cvta.to.shared.u64 t, %1; cvt.u32.u64 %0, t; }"
        : "=r"(a) : "l"(p));
    return a;
}

static __device__ __forceinline__ void cp_async16(uint32_t dst, const void* src) {
    asm volatile("cp.async.cg.shared.global [%0], [%1], 16;"
                 :: "r"(dst), "l"(src) : "memory");
}
static __device__ __forceinline__ void cp_commit() {
    asm volatile("cp.async.commit_group;" ::: "memory");
}
template <int N>
static __device__ __forceinline__ void cp_wait() {
    asm volatile("cp.async.wait_group %0;" :: "n"(N) : "memory");
}

static __device__ __forceinline__ void ldsm_x4(uint32_t& r0, uint32_t& r1,
                                               uint32_t& r2, uint32_t& r3,
                                               uint32_t addr) {
    asm volatile("ldmatrix.sync.aligned.m8n8.x4.shared.b16 {%0,%1,%2,%3}, [%4];"
                 : "=r"(r0), "=r"(r1), "=r"(r2), "=r"(r3) : "r"(addr));
}

static __device__ __forceinline__ void mma_f16(float* d, const uint32_t* a,
                                               const uint32_t* b) {
    asm volatile(
        "mma.sync.aligned.m16n8k16.row.col.f32.f16.f16.f32 "
        "{%0,%1,%2,%3}, {%4,%5,%6,%7}, {%8,%9}, {%0,%1,%2,%3};"
        : "+f"(d[0]), "+f"(d[1]), "+f"(d[2]), "+f"(d[3])
        : "r"(a[0]), "r"(a[1]), "r"(a[2]), "r"(a[3]), "r"(b[0]), "r"(b[1]));
}

static __device__ __forceinline__ void sts64(uint32_t addr, uint32_t lo, uint32_t hi) {
    asm volatile("st.shared.v2.b32 [%0], {%1,%2};"
                 :: "r"(addr), "r"(lo), "r"(hi) : "memory");
}

static __device__ __forceinline__ uint32_t swz(uint32_t off) {
    return off ^ ((off >> 3) & 0x70);
}

static __device__ __forceinline__ uint32_t h2_as_u32(__half2 h) {
    union { __half2 h2; uint32_t u; } c;
    c.h2 = h;
    return c.u;
}

// ---------------------------------------------------------------------------
// prep1: Yt_h[b*64+o][j] = fp16( sum_f x[b,j,f] * W2[o,f] ); block 0 also
// computes the fused bias c[o] = b_out[o] + sum_f nl_b[f]*w_out[o,f].
// ---------------------------------------------------------------------------
__global__ void __launch_bounds__(256) prep1_kernel(const float* __restrict__ x,
                                                    const float* __restrict__ nl_w,
                                                    const float* __restrict__ nl_b,
                                                    const float* __restrict__ w_out,
                                                    const float* __restrict__ b_out) {
    __shared__ float xs[BATCH][JT][FEAT];
    __shared__ float w2s[ODIM * (FEAT + 1)];
    const int tid = threadIdx.x;
    const int j0 = blockIdx.x * JT;

    if (blockIdx.x == 0 && tid >= 64 && tid < 128) {
        int o = tid - 64;
        float a = b_out[o];
#pragma unroll 8
        for (int f = 0; f < FEAT; f++) a += nl_b[f] * w_out[o * FEAT + f];
        g_c[o] = a;
    }

    for (int i = tid; i < ODIM * FEAT; i += 256) {
        int o = i >> 6, f = i & 63;
        w2s[o * (FEAT + 1) + f] = INV_SQRT2F * nl_w[f] * w_out[i];
    }

    for (int i4 = tid; i4 < BATCH * JT * (FEAT / 4); i4 += 256) {
        int b = i4 >> 8;
        int r = i4 & 255;
        int j = r >> 4;
        int f4 = r & 15;
        ((float4*)&xs[b][j][0])[f4] =
            ((const float4*)(x + ((size_t)b * NODES + j0 + j) * FEAT))[f4];
    }
    __syncthreads();

    const int o = tid & 63;
    const int b = tid >> 6;

    float w2r[FEAT];
#pragma unroll
    for (int f = 0; f < FEAT; f++) w2r[f] = w2s[o * (FEAT + 1) + f];

    union { __half h[JT]; uint4 u[2]; } ov;
#pragma unroll
    for (int j = 0; j < JT; j++) {
        float acc = 0.f;
#pragma unroll
        for (int f4 = 0; f4 < FEAT / 4; f4++) {
            float4 xv = ((float4*)&xs[b][j][0])[f4];
            acc += xv.x * w2r[f4 * 4 + 0];
            acc += xv.y * w2r[f4 * 4 + 1];
            acc += xv.z * w2r[f4 * 4 + 2];
            acc += xv.w * w2r[f4 * 4 + 3];
        }
        ov.h[j] = __float2half_rn(acc);
    }

    __half* dst = g_Yt_h + (size_t)(b * ODIM + o) * NODES + j0;
    ((uint4*)dst)[0] = ov.u[0];
    ((uint4*)dst)[1] = ov.u[1];
}

// ---------------------------------------------------------------------------
// Fused split-K GEMM: part[ks] = fp16(adj*2^13)[Kslice] @ Yt_h[Kslice]^T
// grid 256 = (ks 2) x (n 2) x (m 64); block 256 (8 warps: 2m x 4n, 64x32)
// ---------------------------------------------------------------------------
__global__ void __launch_bounds__(256, 2)
gemm_kernel(const float* __restrict__ adj) {
    extern __shared__ char dynsmem[];

    const int tid = threadIdx.x;
    const int wid = tid >> 5;
    const int lane = tid & 31;
    const int ks = blockIdx.x & 1;
    const int n0 = ((blockIdx.x >> 1) & 1) * NT;
    const int m0 = (blockIdx.x >> 2) * MT;
    const int k0 = ks * (NODES / KSPLIT);
    const int wm = wid >> 2;     // 0..1  (m band of 64)
    const int wn = wid & 3;      // 0..3  (n band of 32)

    const uint32_t smem0 = smem_u32(dynsmem);

    // ---- A producer (fp32 LDG, coalesced): fseg = tid&15, r0 = tid>>4 ----
    const int fseg = tid & 15;           // 16B fp32 segment within 64-float row
    const int r0 = tid >> 4;             // base row 0..15 (t adds 16t)
    const float* aptr = adj + (size_t)(m0 + r0) * NODES + k0 + fseg * 4;
    // fp16 STS.64 address: swz(r*128 + fseg*8) = r*128 + ((fseg>>1)^(r&7))*16
    //                      + (fseg&1)*8; rows r0+16t share (r&7).
    const uint32_t abase = (uint32_t)(r0 * 128 + (((fseg >> 1) ^ (r0 & 7)) * 16)
                                      + (fseg & 1) * 8);

    // ---- B producer (cp.async): rb0 = tid>>3, sg = tid&7, rows rb0+32t ----
    const int rb0 = tid >> 3;
    const int sg = tid & 7;
    const uint32_t bbase = (uint32_t)A_BYTES +
        (uint32_t)(rb0 * 128 + ((sg ^ (rb0 & 7)) * 16));
    const __half* bptr = g_Yt_h + (size_t)(n0 + rb0) * NODES + k0 + sg * 8;

    // ---- consumer fragment offsets (pre-swizzled) — proven R8/R10/R11 ----
    uint32_t pa[4];
    {
        int r15 = lane & 15;
        int h = lane >> 4;
#pragma unroll
        for (int mi = 0; mi < 4; mi++)
            pa[mi] = swz((uint32_t)((wm * 64 + mi * 16 + r15) * 128 + h * 16));
    }
    uint32_t pb[2];
    {
        int tile_sel = lane >> 4;
        int h = (lane >> 3) & 1;
        int rn = lane & 7;
#pragma unroll
        for (int nj = 0; nj < 2; nj++)
            pb[nj] = swz((uint32_t)((wn * 32 + (nj * 2 + tile_sel) * 8 + rn) * 128 + h * 16));
    }

    float acc[4][4][4];
#pragma unroll
    for (int mi = 0; mi < 4; mi++)
#pragma unroll
        for (int ni = 0; ni < 4; ni++)
#pragma unroll
            for (int q = 0; q < 4; q++) acc[mi][ni][q] = 0.f;

    auto ldgA = [&](int c, float4* av) {
#pragma unroll
        for (int t = 0; t < 8; t++)
            av[t] = *(const float4*)(aptr + (size_t)t * 16 * NODES + c * KCH);
    };
    auto stsA = [&](int c, const float4* av) {
        const uint32_t sb = smem0 + (uint32_t)(c % NSTG) * STAGE_BYTES;
#pragma unroll
        for (int t = 0; t < 8; t++) {
            float4 v = av[t];
            sts64(sb + abase + (uint32_t)t * 2048,
                  h2_as_u32(__floats2half2_rn(v.x * ADJ_SCALE, v.y * ADJ_SCALE)),
                  h2_as_u32(__floats2half2_rn(v.z * ADJ_SCALE, v.w * ADJ_SCALE)));
        }
    };
    auto loadB = [&](int c) {
        const uint32_t sb = smem0 + (uint32_t)(c % NSTG) * STAGE_BYTES;
#pragma unroll
        for (int t = 0; t < 4; t++)
            cp_async16(sb + bbase + (uint32_t)t * 4096,
                       bptr + (size_t)t * 32 * NODES + c * KCH);
    };

    // ---- prologue: chunks 0,1 fully staged ----
    {
        float4 av[8];
        ldgA(0, av); stsA(0, av);
        loadB(0); cp_commit();
        ldgA(1, av); stsA(1, av);
        loadB(1); cp_commit();
    }

    uint32_t fa[4][4];
    uint32_t fb[4][2];

    for (int i = 0; i < KPC; i++) {
        cp_wait<1>();            // B chunk i resident
        __syncthreads();         // readers of stage (i+2)%3 (iter i-1) passed

        const uint32_t sbase = smem0 + (uint32_t)(i % NSTG) * STAGE_BYTES;
        const int pc = i + 2;

        float4 av[8];
        if (pc < KPC) ldgA(pc, av);     // issue LDGs early (DRAM latency)
        if (pc < KPC) loadB(pc);
        cp_commit();                    // unconditional: fixed group count

        auto fetch = [&](int s) {
            const uint32_t xo = (uint32_t)s << 5;   // k16 step, XOR-safe
#pragma unroll
            for (int mi = 0; mi < 4; mi++)
                ldsm_x4(fa[mi][0], fa[mi][1], fa[mi][2], fa[mi][3],
                        sbase + (pa[mi] ^ xo));
#pragma unroll
            for (int nj = 0; nj < 2; nj++) {
                uint32_t r0_, r1_, r2_, r3_;
                ldsm_x4(r0_, r1_, r2_, r3_, sbase + A_BYTES + (pb[nj] ^ xo));
                fb[nj * 2 + 0][0] = r0_;
                fb[nj * 2 + 0][1] = r1_;
                fb[nj * 2 + 1][0] = r2_;
                fb[nj * 2 + 1][1] = r3_;
            }
        };

#pragma unroll
        for (int s = 0; s < 4; s++) {     // 4 k16 steps, single-buffered frags
            fetch(s);
#pragma unroll
            for (int mi = 0; mi < 4; mi++)
#pragma unroll
                for (int ni = 0; ni < 4; ni++)
                    mma_f16(acc[mi][ni], fa[mi], fb[ni]);
            if (s == 1 && pc < KPC) stsA(pc, av);  // cvt+STS mid-iteration:
                                                   // ~500cyc after LDG issue
        }
        // no tail barrier: next head sync orders stage reuse
    }

    // ---- epilogue: raw partial sums to g_part[ks] ----
    const int qr = lane >> 2;
    const int qc = lane & 3;
    float* part = &g_part[ks][0];
#pragma unroll
    for (int mi = 0; mi < 4; mi++) {
        const int row0 = m0 + wm * 64 + mi * 16 + qr;
#pragma unroll
        for (int ni = 0; ni < 4; ni++) {
            const int ng = n0 + wn * 32 + ni * 8 + qc * 2;
            const int b = ng >> 6;
            const int o = ng & 63;
            float* d0 = part + ((size_t)b * NODES + row0) * ODIM + o;
            *(float2*)d0 = make_float2(acc[mi][ni][0], acc[mi][ni][1]);
            *(float2*)(d0 + 8 * ODIM) = make_float2(acc[mi][ni][2], acc[mi][ni][3]);
        }
    }
}

// ---------------------------------------------------------------------------
// reduce: out = (part0 + part1) * 2^-13 + c[o]
// ---------------------------------------------------------------------------
__global__ void __launch_bounds__(256) reduce_kernel(float* __restrict__ out) {
    const size_t i4 = (size_t)blockIdx.x * 256 + threadIdx.x;  // float4 index
    const size_t e = i4 * 4;
    float4 p0 = *(const float4*)&g_part[0][e];
    float4 p1 = *(const float4*)&g_part[1][e];
    float4 c = *(const float4*)(g_c + (int)(e & 63));
    float4 r;
    r.x = (p0.x + p1.x) * OUT_SCALE + c.x;
    r.y = (p0.y + p1.y) * OUT_SCALE + c.y;
    r.z = (p0.z + p1.z) * OUT_SCALE + c.z;
    r.w = (p0.w + p1.w) * OUT_SCALE + c.w;
    *(float4*)(out + e) = r;
}

// ---------------------------------------------------------------------------
// launch
// ---------------------------------------------------------------------------
extern "C" void kernel_launch(void* const* d_in, const int* in_sizes, int n_in,
                              void* d_out, int out_size) {
    (void)in_sizes; (void)n_in; (void)out_size;
    const float* x     = (const float*)d_in[0];
    const float* adj   = (const float*)d_in[1];
    const float* nl_w  = (const float*)d_in[2];
    const float* nl_b  = (const float*)d_in[3];
    const float* w_out = (const float*)d_in[4];
    const float* b_out = (const float*)d_in[5];
    float* out = (float*)d_out;

    prep1_kernel<<<NODES / JT, 256>>>(x, nl_w, nl_b, w_out, b_out);

    cudaFuncSetAttribute(gemm_kernel,
                         cudaFuncAttributeMaxDynamicSharedMemorySize, SMEM_DYN);
    gemm_kernel<<<256, 256, SMEM_DYN>>>(adj);

    reduce_kernel<<<(NCOLS * NODES) / (256 * 4), 256>>>(out);
}